// round 3
// baseline (speedup 1.0000x reference)
#include <cuda_runtime.h>

// ---------------------------------------------------------------------------
// GCN_50672024159115 — fp32 tiled dense + L2-resident atomic SpMM
// edge_index is int32 (JAX x64 disabled => astype(int64) yields int32).
// ---------------------------------------------------------------------------

constexpr int DIM    = 64;
constexpr int DIMF   = 128;
constexpr int NUSER  = 50000;
constexpr int NITEM  = 50000;
constexpr int NN     = NUSER + NITEM;     // 100000
constexpr int EMAX   = 1600000;

static inline int cdiv(int a, int b) { return (a + b - 1) / b; }

// -------------------------- scratch (device globals) -----------------------
__device__ __align__(16) float g_x  [NN * DIM];
__device__ __align__(16) float g_xw [NN * DIM];
__device__ __align__(16) float g_agg[NN * DIM];
__device__ __align__(16) float g_h  [NN * DIM];
__device__ __align__(16) float g_xh [NN * DIM];
__device__ float g_dinv[NN];
__device__ int   g_deg [NN];
__device__ int   g_src [EMAX];
__device__ int   g_dst [EMAX];
__device__ float g_ew  [EMAX];

// buffer IDs: 0=x 1=xw 2=agg 3=h 4=xh, -1 = use external pointer
__device__ __forceinline__ float* sel(float* ext, int id) {
    switch (id) {
        case 0: return g_x;
        case 1: return g_xw;
        case 2: return g_agg;
        case 3: return g_h;
        case 4: return g_xh;
        default: return ext;
    }
}

// ------------------------------ prep kernels --------------------------------
__global__ void k_init_deg(int n) {
    int i = blockIdx.x * blockDim.x + threadIdx.x;
    if (i < n) g_deg[i] = 1;                  // self-loop contributes 1 to deg
}

__global__ void k_prep_edges(const int* __restrict__ ei, int E) {
    int e = blockIdx.x * blockDim.x + threadIdx.x;
    if (e >= E) return;
    int s = ei[e];
    int d = ei[E + e];
    g_src[e] = s;
    g_dst[e] = d;
    atomicAdd(&g_deg[s], 1);
}

__global__ void k_dinv(int n) {
    int i = blockIdx.x * blockDim.x + threadIdx.x;
    if (i < n) g_dinv[i] = rsqrtf((float)g_deg[i]);
}

__global__ void k_edge_w(int E) {
    int e = blockIdx.x * blockDim.x + threadIdx.x;
    if (e < E) g_ew[e] = g_dinv[g_src[e]] * g_dinv[g_dst[e]];
}

__global__ void k_copy_pref(const float4* __restrict__ in, int n4) {
    int i = blockIdx.x * blockDim.x + threadIdx.x;
    if (i < n4) ((float4*)g_x)[i] = in[i];
}

// ----------------------------- row L2-normalize -----------------------------
// one warp per row; lane handles 2 consecutive floats
__global__ void k_norm(int in_id, int out_id, int nrows, int do_lrelu) {
    const float* in  = sel(nullptr, in_id);
    float*       out = sel(nullptr, out_id);
    int gid  = blockIdx.x * blockDim.x + threadIdx.x;
    int row  = gid >> 5;
    int lane = gid & 31;
    if (row >= nrows) return;
    float2 v = *(const float2*)(in + (size_t)row * DIM + lane * 2);
    float ss = v.x * v.x + v.y * v.y;
    #pragma unroll
    for (int o = 16; o > 0; o >>= 1) ss += __shfl_xor_sync(0xffffffffu, ss, o);
    float s = 1.0f / fmaxf(sqrtf(ss), 1e-12f);
    float a = v.x * s, b = v.y * s;
    if (do_lrelu) {
        a = a > 0.0f ? a : 0.01f * a;
        b = b > 0.0f ? b : 0.01f * b;
    }
    *(float2*)(out + (size_t)row * DIM + lane * 2) = make_float2(a, b);
}

// ------------------- agg init: bias + self-loop contribution ----------------
// agg[i] = b + dinv[i]^2 * xw[i]
__global__ void k_init_agg(const float* __restrict__ bias, int n) {
    int idx = blockIdx.x * blockDim.x + threadIdx.x;   // n*16 float4 chunks
    if (idx >= n * 16) return;
    int i = idx >> 4, c = idx & 15;
    float di = g_dinv[i];
    float w  = di * di;
    float4 x = ((const float4*)g_xw)[idx];
    float4 b = ((const float4*)bias)[c];
    ((float4*)g_agg)[idx] = make_float4(b.x + w * x.x, b.y + w * x.y,
                                        b.z + w * x.z, b.w + w * x.w);
}

// ------------------------------ edge scatter --------------------------------
// agg[dst] += w_e * xw[src]; one thread per (edge, float4-chunk)
__global__ void k_scatter(int E) {
    int idx = blockIdx.x * blockDim.x + threadIdx.x;
    if (idx >= E * 16) return;
    int e = idx >> 4, c = idx & 15;
    int s = g_src[e];
    int d = g_dst[e];
    float w = g_ew[e];
    float4 v = ((const float4*)g_xw)[s * 16 + c];
    float* p = (float*)(((float4*)g_agg) + (d * 16 + c));
    asm volatile("red.global.add.v4.f32 [%0], {%1,%2,%3,%4};"
                 :: "l"(p), "f"(w * v.x), "f"(w * v.y), "f"(w * v.z), "f"(w * v.w)
                 : "memory");
}

// ------------------------------- dense GEMM ---------------------------------
// C[nrows,64] = act( A[nrows,K] @ W[K,64] (+bias) ) (+add)
// 256 threads, 64-row tile, 4x4 register blocking.
template<int K, int ACT, int HASB, int HASADD>
__global__ void __launch_bounds__(256)
k_dense(const float* __restrict__ Aext, int a_id,
        const float* __restrict__ W, const float* __restrict__ bias,
        int add_id,
        float* __restrict__ Cext, int c_id, int c_off,
        int nrows) {
    const float* A   = sel((float*)Aext, a_id);
    const float* add = HASADD ? sel(nullptr, add_id) : nullptr;
    float*       C   = sel(Cext, c_id) + c_off;

    __shared__ __align__(16) float As[64][68];
    __shared__ __align__(16) float Ws[64][68];
    int row0 = blockIdx.x * 64;
    int t  = threadIdx.x;
    int tx = t & 15, ty = t >> 4;
    float acc[4][4] = {};

    for (int kt = 0; kt < K; kt += 64) {
        #pragma unroll
        for (int i = t; i < 64 * 16; i += 256) {
            int r = i >> 4, c4 = i & 15;
            float4 v = make_float4(0.f, 0.f, 0.f, 0.f);
            if (row0 + r < nrows)
                v = *(const float4*)&A[(size_t)(row0 + r) * K + kt + c4 * 4];
            *(float4*)&As[r][c4 * 4] = v;
        }
        #pragma unroll
        for (int i = t; i < 64 * 16; i += 256) {
            int r = i >> 4, c4 = i & 15;
            *(float4*)&Ws[r][c4 * 4] = *(const float4*)&W[(size_t)(kt + r) * 64 + c4 * 4];
        }
        __syncthreads();

        #pragma unroll 16
        for (int k = 0; k < 64; k++) {
            float a0 = As[ty * 4 + 0][k];
            float a1 = As[ty * 4 + 1][k];
            float a2 = As[ty * 4 + 2][k];
            float a3 = As[ty * 4 + 3][k];
            float4 wv = *(float4*)&Ws[k][tx * 4];
            acc[0][0] += a0 * wv.x; acc[0][1] += a0 * wv.y; acc[0][2] += a0 * wv.z; acc[0][3] += a0 * wv.w;
            acc[1][0] += a1 * wv.x; acc[1][1] += a1 * wv.y; acc[1][2] += a1 * wv.z; acc[1][3] += a1 * wv.w;
            acc[2][0] += a2 * wv.x; acc[2][1] += a2 * wv.y; acc[2][2] += a2 * wv.z; acc[2][3] += a2 * wv.w;
            acc[3][0] += a3 * wv.x; acc[3][1] += a3 * wv.y; acc[3][2] += a3 * wv.z; acc[3][3] += a3 * wv.w;
        }
        __syncthreads();
    }

    float4 bv = make_float4(0.f, 0.f, 0.f, 0.f);
    if (HASB) bv = *(const float4*)&bias[tx * 4];
    #pragma unroll
    for (int i = 0; i < 4; i++) {
        int row = row0 + ty * 4 + i;
        if (row >= nrows) break;
        float4 v;
        v.x = acc[i][0] + bv.x;
        v.y = acc[i][1] + bv.y;
        v.z = acc[i][2] + bv.z;
        v.w = acc[i][3] + bv.w;
        if (ACT) {
            v.x = v.x > 0.0f ? v.x : 0.01f * v.x;
            v.y = v.y > 0.0f ? v.y : 0.01f * v.y;
            v.z = v.z > 0.0f ? v.z : 0.01f * v.z;
            v.w = v.w > 0.0f ? v.w : 0.01f * v.w;
        }
        if (HASADD) {
            float4 a4 = *(const float4*)&add[(size_t)row * DIM + tx * 4];
            v.x += a4.x; v.y += a4.y; v.z += a4.z; v.w += a4.w;
        }
        *(float4*)&C[(size_t)row * DIM + tx * 4] = v;
    }
}

// -------------------------------- launcher ----------------------------------
extern "C" void kernel_launch(void* const* d_in, const int* in_sizes, int n_in,
                              void* d_out, int out_size) {
    const float* features = (const float*)d_in[0];
    const float* pref     = (const float*)d_in[1];
    const int*   ei       = (const int*)d_in[2];      // int32 edge_index [2, E]
    const float* W[22];
    for (int i = 0; i < 22; i++) W[i] = (const float*)d_in[3 + i];
    // 0 mlp_w 1 mlp_b 2 conv1_w 3 conv1_b 4 g1_w 5 g1_b 6 conv2_w 7 conv2_b
    // 8 g2_w 9 g2_b 10 conv4_w 11 conv4_b 12 lin4_w 13 lin4_b 14 g4_w 15 g4_b
    // 16 conv5_w 17 conv5_b 18 lin5_w 19 lin5_b 20 g5_w 21 g5_b
    int E = in_sizes[2] / 2;
    float* out = (float*)d_out;
    (void)n_in; (void)out_size;

    const int TB = 256;
    const int ID_X = 0, ID_XW = 1, ID_AGG = 2, ID_H = 3, ID_XH = 4, EXT = -1;

    // ---- per-launch graph prep (shared by all 4 conv layers) ----
    k_init_deg  <<<cdiv(NN, TB), TB>>>(NN);
    k_prep_edges<<<cdiv(E,  TB), TB>>>(ei, E);
    k_dinv      <<<cdiv(NN, TB), TB>>>(NN);
    k_edge_w    <<<cdiv(E,  TB), TB>>>(E);

    // ---- embedding: x = l2norm(concat(pref, features@mlp_w + mlp_b)) ----
    k_copy_pref<<<cdiv(NUSER * 16, TB), TB>>>((const float4*)pref, NUSER * 16);
    k_dense<DIMF, 0, 1, 0><<<cdiv(NITEM, 64), 256>>>(features, EXT, W[0], W[1], -1,
                                                     nullptr, ID_X, NUSER * DIM, NITEM);
    k_norm<<<cdiv(NN * 32, TB), TB>>>(ID_X, ID_X, NN, 0);

    auto conv = [&](const float* cw, const float* cb) {
        k_dense<DIM, 0, 0, 0><<<cdiv(NN, 64), 256>>>(nullptr, ID_X, cw, nullptr, -1,
                                                     nullptr, ID_XW, 0, NN);
        k_init_agg<<<cdiv(NN * 16, TB), TB>>>(cb, NN);
        k_scatter <<<cdiv(E * 16,  TB), TB>>>(E);
        k_norm    <<<cdiv(NN * 32, TB), TB>>>(ID_AGG, ID_H, NN, 1);  // h = lrelu(l2norm(agg))
    };

    // layer 1
    conv(W[2], W[3]);
    k_dense<DIM, 1, 1, 0><<<cdiv(NN, 64), 256>>>(nullptr, ID_H, W[4], W[5], -1,
                                                 nullptr, ID_X, 0, NN);
    // layer 2
    conv(W[6], W[7]);
    k_dense<DIM, 1, 1, 0><<<cdiv(NN, 64), 256>>>(nullptr, ID_H, W[8], W[9], -1,
                                                 nullptr, ID_X, 0, NN);

    // mu head
    conv(W[10], W[11]);
    k_dense<DIM, 1, 1, 0><<<cdiv(NN, 64), 256>>>(nullptr, ID_X, W[12], W[13], -1,
                                                 nullptr, ID_XH, 0, NN);
    k_dense<DIM, 0, 1, 1><<<cdiv(NN, 64), 256>>>(nullptr, ID_H, W[14], W[15], ID_XH,
                                                 out, EXT, 0, NN);

    // logvar head
    conv(W[16], W[17]);
    k_dense<DIM, 1, 1, 0><<<cdiv(NN, 64), 256>>>(nullptr, ID_X, W[18], W[19], -1,
                                                 nullptr, ID_XH, 0, NN);
    k_dense<DIM, 0, 1, 1><<<cdiv(NN, 64), 256>>>(nullptr, ID_H, W[20], W[21], ID_XH,
                                                 out, EXT, NN * DIM, NN);
}

// round 5
// speedup vs baseline: 1.3975x; 1.3975x over previous
#include <cuda_runtime.h>

// ---------------------------------------------------------------------------
// GCN_50672024159115 — fp32 tiled dense + per-launch dst-CSR gather conv
// (atomic RED scatter replaced by warp-per-row gather with fused
//  bias + self-loop + l2norm + leaky-relu epilogue)
// Identical to Round-3 submission: that round died to a broker/container
// failure before execution, so this is the clean re-measurement.
// ---------------------------------------------------------------------------

constexpr int DIM    = 64;
constexpr int DIMF   = 128;
constexpr int NUSER  = 50000;
constexpr int NITEM  = 50000;
constexpr int NN     = NUSER + NITEM;     // 100000
constexpr int EMAX   = 1600000;
constexpr int SCAN_B = 512;
constexpr int NBLK   = (NN + SCAN_B - 1) / SCAN_B;   // 196

static inline int cdiv(int a, int b) { return (a + b - 1) / b; }

// -------------------------- scratch (device globals) -----------------------
__device__ __align__(16) float g_x  [NN * DIM];
__device__ __align__(16) float g_xw [NN * DIM];
__device__ __align__(16) float g_h  [NN * DIM];
__device__ __align__(16) float g_xh [NN * DIM];
__device__ float g_dinv[NN];
__device__ int   g_deg [NN];
__device__ int   g_cnt [NN];          // dst histogram
__device__ int   g_cur [NN];          // fill cursor
__device__ int   g_rowptr[NN + 1];
__device__ int   g_part [NBLK];       // scan partials
__device__ int   g_src [EMAX];
__device__ int   g_dst [EMAX];
__device__ int   g_cs_src[EMAX];      // CSR column (src) per dst-sorted edge
__device__ float g_cs_w  [EMAX];      // dinv[src] per CSR entry

// buffer IDs: 0=x 1=xw 2=h 3=xh, -1 = external pointer
__device__ __forceinline__ float* sel(float* ext, int id) {
    switch (id) {
        case 0: return g_x;
        case 1: return g_xw;
        case 2: return g_h;
        case 3: return g_xh;
        default: return ext;
    }
}

// ------------------------------ prep kernels --------------------------------
__global__ void k_zero(int n) {
    int i = blockIdx.x * blockDim.x + threadIdx.x;
    if (i < n) { g_deg[i] = 1; g_cnt[i] = 0; g_cur[i] = 0; }
}

__global__ void k_count(const int* __restrict__ ei, int E) {
    int e = blockIdx.x * blockDim.x + threadIdx.x;
    if (e >= E) return;
    int s = ei[e];
    int d = ei[E + e];
    g_src[e] = s;
    g_dst[e] = d;
    atomicAdd(&g_deg[s], 1);      // reference degree: count of src occurrences
    atomicAdd(&g_cnt[d], 1);      // CSR histogram over dst
}

__global__ void k_dinv(int n) {
    int i = blockIdx.x * blockDim.x + threadIdx.x;
    if (i < n) g_dinv[i] = rsqrtf((float)g_deg[i]);
}

// ---- 3-phase exclusive scan of g_cnt -> g_rowptr ----
__global__ void k_scan_a() {
    __shared__ int sm[SCAN_B];
    int tid = threadIdx.x;
    int i = blockIdx.x * SCAN_B + tid;
    int v = (i < NN) ? g_cnt[i] : 0;
    sm[tid] = v;
    __syncthreads();
    #pragma unroll
    for (int off = 1; off < SCAN_B; off <<= 1) {
        int t = (tid >= off) ? sm[tid - off] : 0;
        __syncthreads();
        sm[tid] += t;
        __syncthreads();
    }
    if (i < NN) g_rowptr[i] = sm[tid] - v;            // exclusive within block
    if (tid == SCAN_B - 1) g_part[blockIdx.x] = sm[tid];
}

__global__ void k_scan_b() {    // single block of 256 threads scans NBLK partials
    __shared__ int sm[256];
    int tid = threadIdx.x;
    int v = (tid < NBLK) ? g_part[tid] : 0;
    sm[tid] = v;
    __syncthreads();
    #pragma unroll
    for (int off = 1; off < 256; off <<= 1) {
        int t = (tid >= off) ? sm[tid - off] : 0;
        __syncthreads();
        sm[tid] += t;
        __syncthreads();
    }
    if (tid < NBLK) g_part[tid] = sm[tid] - v;        // exclusive
}

__global__ void k_scan_c(int E) {
    int i = blockIdx.x * blockDim.x + threadIdx.x;
    if (i < NN) g_rowptr[i] += g_part[i / SCAN_B];
    if (i == 0) g_rowptr[NN] = E;
}

__global__ void k_fill(int E) {
    int e = blockIdx.x * blockDim.x + threadIdx.x;
    if (e >= E) return;
    int s = g_src[e];
    int d = g_dst[e];
    int pos = g_rowptr[d] + atomicAdd(&g_cur[d], 1);
    g_cs_src[pos] = s;
    g_cs_w[pos]   = g_dinv[s];
}

__global__ void k_copy_pref(const float4* __restrict__ in, int n4) {
    int i = blockIdx.x * blockDim.x + threadIdx.x;
    if (i < n4) ((float4*)g_x)[i] = in[i];
}

// ----------------------------- row L2-normalize -----------------------------
__global__ void k_norm(int in_id, int out_id, int nrows) {
    const float* in  = sel(nullptr, in_id);
    float*       out = sel(nullptr, out_id);
    int gid  = blockIdx.x * blockDim.x + threadIdx.x;
    int row  = gid >> 5;
    int lane = gid & 31;
    if (row >= nrows) return;
    float2 v = *(const float2*)(in + (size_t)row * DIM + lane * 2);
    float ss = v.x * v.x + v.y * v.y;
    #pragma unroll
    for (int o = 16; o > 0; o >>= 1) ss += __shfl_xor_sync(0xffffffffu, ss, o);
    float s = 1.0f / fmaxf(sqrtf(ss), 1e-12f);
    *(float2*)(out + (size_t)row * DIM + lane * 2) = make_float2(v.x * s, v.y * s);
}

// ---------------------- CSR gather conv (fused epilogue) --------------------
// h[d] = lrelu( l2norm( dinv[d]*( sum_{e in CSR[d]} dinv[s_e]*xw[s_e]
//                                 + dinv[d]*xw[d] ) + bias ) )
__global__ void __launch_bounds__(256)
k_gather(const float* __restrict__ bias) {
    int gw   = (blockIdx.x * blockDim.x + threadIdx.x) >> 5;
    int lane = threadIdx.x & 31;
    if (gw >= NN) return;
    int start = g_rowptr[gw];
    int end   = g_rowptr[gw + 1];
    float a0 = 0.f, a1 = 0.f;
    for (int base = start; base < end; base += 32) {
        int e = base + lane;
        int s = 0; float w = 0.f;
        if (e < end) { s = g_cs_src[e]; w = g_cs_w[e]; }
        int m = min(32, end - base);
        for (int j = 0; j < m; j++) {
            int   sj = __shfl_sync(0xffffffffu, s, j);
            float wj = __shfl_sync(0xffffffffu, w, j);
            float2 v = *(const float2*)&g_xw[(size_t)sj * DIM + lane * 2];
            a0 += wj * v.x;
            a1 += wj * v.y;
        }
    }
    float dd = g_dinv[gw];
    float2 xv = *(const float2*)&g_xw[(size_t)gw * DIM + lane * 2];
    float2 bv = *(const float2*)&bias[lane * 2];
    a0 = dd * (a0 + dd * xv.x) + bv.x;
    a1 = dd * (a1 + dd * xv.y) + bv.y;
    float ss = a0 * a0 + a1 * a1;
    #pragma unroll
    for (int o = 16; o > 0; o >>= 1) ss += __shfl_xor_sync(0xffffffffu, ss, o);
    float sc = 1.0f / fmaxf(sqrtf(ss), 1e-12f);
    a0 *= sc; a1 *= sc;
    a0 = a0 > 0.f ? a0 : 0.01f * a0;
    a1 = a1 > 0.f ? a1 : 0.01f * a1;
    *(float2*)&g_h[(size_t)gw * DIM + lane * 2] = make_float2(a0, a1);
}

// ------------------------------- dense GEMM ---------------------------------
// C[nrows,64] = act( A[nrows,K] @ W[K,64] (+bias) ) (+add)
template<int K, int ACT, int HASB, int HASADD>
__global__ void __launch_bounds__(256)
k_dense(const float* __restrict__ Aext, int a_id,
        const float* __restrict__ W, const float* __restrict__ bias,
        int add_id,
        float* __restrict__ Cext, int c_id, int c_off,
        int nrows) {
    const float* A   = sel((float*)Aext, a_id);
    const float* add = HASADD ? sel(nullptr, add_id) : nullptr;
    float*       C   = sel(Cext, c_id) + c_off;

    __shared__ __align__(16) float As[64][68];
    __shared__ __align__(16) float Ws[64][68];
    int row0 = blockIdx.x * 64;
    int t  = threadIdx.x;
    int tx = t & 15, ty = t >> 4;
    float acc[4][4] = {};

    for (int kt = 0; kt < K; kt += 64) {
        #pragma unroll
        for (int i = t; i < 64 * 16; i += 256) {
            int r = i >> 4, c4 = i & 15;
            float4 v = make_float4(0.f, 0.f, 0.f, 0.f);
            if (row0 + r < nrows)
                v = *(const float4*)&A[(size_t)(row0 + r) * K + kt + c4 * 4];
            *(float4*)&As[r][c4 * 4] = v;
        }
        #pragma unroll
        for (int i = t; i < 64 * 16; i += 256) {
            int r = i >> 4, c4 = i & 15;
            *(float4*)&Ws[r][c4 * 4] = *(const float4*)&W[(size_t)(kt + r) * 64 + c4 * 4];
        }
        __syncthreads();

        #pragma unroll 16
        for (int k = 0; k < 64; k++) {
            float a0 = As[ty * 4 + 0][k];
            float a1 = As[ty * 4 + 1][k];
            float a2 = As[ty * 4 + 2][k];
            float a3 = As[ty * 4 + 3][k];
            float4 wv = *(float4*)&Ws[k][tx * 4];
            acc[0][0] += a0 * wv.x; acc[0][1] += a0 * wv.y; acc[0][2] += a0 * wv.z; acc[0][3] += a0 * wv.w;
            acc[1][0] += a1 * wv.x; acc[1][1] += a1 * wv.y; acc[1][2] += a1 * wv.z; acc[1][3] += a1 * wv.w;
            acc[2][0] += a2 * wv.x; acc[2][1] += a2 * wv.y; acc[2][2] += a2 * wv.z; acc[2][3] += a2 * wv.w;
            acc[3][0] += a3 * wv.x; acc[3][1] += a3 * wv.y; acc[3][2] += a3 * wv.z; acc[3][3] += a3 * wv.w;
        }
        __syncthreads();
    }

    float4 bv = make_float4(0.f, 0.f, 0.f, 0.f);
    if (HASB) bv = *(const float4*)&bias[tx * 4];
    #pragma unroll
    for (int i = 0; i < 4; i++) {
        int row = row0 + ty * 4 + i;
        if (row >= nrows) break;
        float4 v;
        v.x = acc[i][0] + bv.x;
        v.y = acc[i][1] + bv.y;
        v.z = acc[i][2] + bv.z;
        v.w = acc[i][3] + bv.w;
        if (ACT) {
            v.x = v.x > 0.0f ? v.x : 0.01f * v.x;
            v.y = v.y > 0.0f ? v.y : 0.01f * v.y;
            v.z = v.z > 0.0f ? v.z : 0.01f * v.z;
            v.w = v.w > 0.0f ? v.w : 0.01f * v.w;
        }
        if (HASADD) {
            float4 a4 = *(const float4*)&add[(size_t)row * DIM + tx * 4];
            v.x += a4.x; v.y += a4.y; v.z += a4.z; v.w += a4.w;
        }
        *(float4*)&C[(size_t)row * DIM + tx * 4] = v;
    }
}

// -------------------------------- launcher ----------------------------------
extern "C" void kernel_launch(void* const* d_in, const int* in_sizes, int n_in,
                              void* d_out, int out_size) {
    const float* features = (const float*)d_in[0];
    const float* pref     = (const float*)d_in[1];
    const int*   ei       = (const int*)d_in[2];      // int32 edge_index [2, E]
    const float* W[22];
    for (int i = 0; i < 22; i++) W[i] = (const float*)d_in[3 + i];
    int E = in_sizes[2] / 2;
    float* out = (float*)d_out;
    (void)n_in; (void)out_size;

    const int TB = 256;
    const int ID_X = 0, ID_XW = 1, ID_H = 2, ID_XH = 3, EXT = -1;

    // ---- per-launch prep: degrees + dst-CSR (shared by all 4 conv layers) ----
    k_zero  <<<cdiv(NN, TB), TB>>>(NN);
    k_count <<<cdiv(E,  TB), TB>>>(ei, E);
    k_dinv  <<<cdiv(NN, TB), TB>>>(NN);
    k_scan_a<<<NBLK, SCAN_B>>>();
    k_scan_b<<<1, 256>>>();
    k_scan_c<<<cdiv(NN, TB), TB>>>(E);
    k_fill  <<<cdiv(E,  TB), TB>>>(E);

    // ---- embedding: x = l2norm(concat(pref, features@mlp_w + mlp_b)) ----
    k_copy_pref<<<cdiv(NUSER * 16, TB), TB>>>((const float4*)pref, NUSER * 16);
    k_dense<DIMF, 0, 1, 0><<<cdiv(NITEM, 64), 256>>>(features, EXT, W[0], W[1], -1,
                                                     nullptr, ID_X, NUSER * DIM, NITEM);
    k_norm<<<cdiv(NN * 32, TB), TB>>>(ID_X, ID_X, NN);

    auto conv = [&](const float* cw, const float* cb) {
        k_dense<DIM, 0, 0, 0><<<cdiv(NN, 64), 256>>>(nullptr, ID_X, cw, nullptr, -1,
                                                     nullptr, ID_XW, 0, NN);
        k_gather<<<cdiv(NN * 32, TB), TB>>>(cb);      // h = lrelu(l2norm(conv))
    };

    // layer 1
    conv(W[2], W[3]);
    k_dense<DIM, 1, 1, 0><<<cdiv(NN, 64), 256>>>(nullptr, ID_H, W[4], W[5], -1,
                                                 nullptr, ID_X, 0, NN);
    // layer 2
    conv(W[6], W[7]);
    k_dense<DIM, 1, 1, 0><<<cdiv(NN, 64), 256>>>(nullptr, ID_H, W[8], W[9], -1,
                                                 nullptr, ID_X, 0, NN);

    // mu head
    conv(W[10], W[11]);
    k_dense<DIM, 1, 1, 0><<<cdiv(NN, 64), 256>>>(nullptr, ID_X, W[12], W[13], -1,
                                                 nullptr, ID_XH, 0, NN);
    k_dense<DIM, 0, 1, 1><<<cdiv(NN, 64), 256>>>(nullptr, ID_H, W[14], W[15], ID_XH,
                                                 out, EXT, 0, NN);

    // logvar head
    conv(W[16], W[17]);
    k_dense<DIM, 1, 1, 0><<<cdiv(NN, 64), 256>>>(nullptr, ID_X, W[18], W[19], -1,
                                                 nullptr, ID_XH, 0, NN);
    k_dense<DIM, 0, 1, 1><<<cdiv(NN, 64), 256>>>(nullptr, ID_H, W[20], W[21], ID_XH,
                                                 out, EXT, NN * DIM, NN);
}

// round 8
// speedup vs baseline: 1.7973x; 1.2860x over previous
#include <cuda_runtime.h>
#include <cuda_fp16.h>
#include <cstdint>

// ---------------------------------------------------------------------------
// GCN_50672024159115 — fp16 HMMA dense GEMMs + dst-CSR fp16 gather conv
// (byte-identical resubmission of Round 7; that round died to a
//  broker/container failure before the kernel ever compiled or ran)
// ---------------------------------------------------------------------------

constexpr int DIM    = 64;
constexpr int DIMF   = 128;
constexpr int NUSER  = 50000;
constexpr int NITEM  = 50000;
constexpr int NN     = NUSER + NITEM;     // 100000
constexpr int EMAX   = 1600000;
constexpr int SCAN_B = 512;
constexpr int NBLK   = (NN + SCAN_B - 1) / SCAN_B;   // 196

static inline int cdiv(int a, int b) { return (a + b - 1) / b; }

// -------------------------- scratch (device globals) -----------------------
__device__ __align__(16) float  g_x  [NN * DIM];
__device__ __align__(16) __half g_xwh[NN * DIM];     // conv xw in fp16
__device__ __align__(16) float  g_h  [NN * DIM];
__device__ __align__(16) float  g_xh [NN * DIM];
__device__ float g_dinv[NN];
__device__ int   g_deg [NN];
__device__ int   g_cnt [NN];
__device__ int   g_cur [NN];
__device__ int   g_rowptr[NN + 1];
__device__ int   g_part [NBLK];
__device__ int   g_src [EMAX];
__device__ int   g_dst [EMAX];
__device__ int   g_cs_src[EMAX];
__device__ float g_cs_w  [EMAX];

// buffer IDs: 0=x 1=h 2=xh, -1 = external
__device__ __forceinline__ float* sel(float* ext, int id) {
    switch (id) {
        case 0: return g_x;
        case 1: return g_h;
        case 2: return g_xh;
        default: return ext;
    }
}

// ------------------------------ prep kernels --------------------------------
__global__ void k_zero(int n) {
    int i = blockIdx.x * blockDim.x + threadIdx.x;
    if (i < n) { g_deg[i] = 1; g_cnt[i] = 0; g_cur[i] = 0; }
}

__global__ void k_count(const int* __restrict__ ei, int E) {
    int e = blockIdx.x * blockDim.x + threadIdx.x;
    if (e >= E) return;
    int s = ei[e];
    int d = ei[E + e];
    g_src[e] = s;
    g_dst[e] = d;
    atomicAdd(&g_deg[s], 1);
    atomicAdd(&g_cnt[d], 1);
}

__global__ void k_dinv(int n) {
    int i = blockIdx.x * blockDim.x + threadIdx.x;
    if (i < n) g_dinv[i] = rsqrtf((float)g_deg[i]);
}

__global__ void k_scan_a() {
    __shared__ int sm[SCAN_B];
    int tid = threadIdx.x;
    int i = blockIdx.x * SCAN_B + tid;
    int v = (i < NN) ? g_cnt[i] : 0;
    sm[tid] = v;
    __syncthreads();
    #pragma unroll
    for (int off = 1; off < SCAN_B; off <<= 1) {
        int t = (tid >= off) ? sm[tid - off] : 0;
        __syncthreads();
        sm[tid] += t;
        __syncthreads();
    }
    if (i < NN) g_rowptr[i] = sm[tid] - v;
    if (tid == SCAN_B - 1) g_part[blockIdx.x] = sm[tid];
}

__global__ void k_scan_b() {
    __shared__ int sm[256];
    int tid = threadIdx.x;
    int v = (tid < NBLK) ? g_part[tid] : 0;
    sm[tid] = v;
    __syncthreads();
    #pragma unroll
    for (int off = 1; off < 256; off <<= 1) {
        int t = (tid >= off) ? sm[tid - off] : 0;
        __syncthreads();
        sm[tid] += t;
        __syncthreads();
    }
    if (tid < NBLK) g_part[tid] = sm[tid] - v;
}

__global__ void k_scan_c(int E) {
    int i = blockIdx.x * blockDim.x + threadIdx.x;
    if (i < NN) g_rowptr[i] += g_part[i / SCAN_B];
    if (i == 0) g_rowptr[NN] = E;
}

__global__ void k_fill(int E) {
    int e = blockIdx.x * blockDim.x + threadIdx.x;
    if (e >= E) return;
    int s = g_src[e];
    int d = g_dst[e];
    int pos = g_rowptr[d] + atomicAdd(&g_cur[d], 1);
    g_cs_src[pos] = s;
    g_cs_w[pos]   = g_dinv[s];
}

__global__ void k_copy_pref(const float4* __restrict__ in, int n4) {
    int i = blockIdx.x * blockDim.x + threadIdx.x;
    if (i < n4) ((float4*)g_x)[i] = in[i];
}

// ----------------------------- row L2-normalize -----------------------------
__global__ void k_norm(int in_id, int out_id, int nrows) {
    const float* in  = sel(nullptr, in_id);
    float*       out = sel(nullptr, out_id);
    int gid  = blockIdx.x * blockDim.x + threadIdx.x;
    int row  = gid >> 5;
    int lane = gid & 31;
    if (row >= nrows) return;
    float2 v = *(const float2*)(in + (size_t)row * DIM + lane * 2);
    float ss = v.x * v.x + v.y * v.y;
    #pragma unroll
    for (int o = 16; o > 0; o >>= 1) ss += __shfl_xor_sync(0xffffffffu, ss, o);
    float s = 1.0f / fmaxf(sqrtf(ss), 1e-12f);
    *(float2*)(out + (size_t)row * DIM + lane * 2) = make_float2(v.x * s, v.y * s);
}

// ---------------------- CSR gather conv (fp16 rows, fused epilogue) ---------
__global__ void __launch_bounds__(256)
k_gather(const float* __restrict__ bias) {
    int gw   = (blockIdx.x * blockDim.x + threadIdx.x) >> 5;
    int lane = threadIdx.x & 31;
    if (gw >= NN) return;
    int start = g_rowptr[gw];
    int end   = g_rowptr[gw + 1];
    float a0 = 0.f, a1 = 0.f;
    for (int base = start; base < end; base += 32) {
        int e = base + lane;
        int s = 0; float w = 0.f;
        if (e < end) { s = g_cs_src[e]; w = g_cs_w[e]; }
        int m = min(32, end - base);
        for (int j = 0; j < m; j++) {
            int   sj = __shfl_sync(0xffffffffu, s, j);
            float wj = __shfl_sync(0xffffffffu, w, j);
            float2 v = __half22float2(*(const half2*)&g_xwh[(size_t)sj * DIM + lane * 2]);
            a0 += wj * v.x;
            a1 += wj * v.y;
        }
    }
    float dd = g_dinv[gw];
    float2 xv = __half22float2(*(const half2*)&g_xwh[(size_t)gw * DIM + lane * 2]);
    float2 bv = *(const float2*)&bias[lane * 2];
    a0 = dd * (a0 + dd * xv.x) + bv.x;
    a1 = dd * (a1 + dd * xv.y) + bv.y;
    float ss = a0 * a0 + a1 * a1;
    #pragma unroll
    for (int o = 16; o > 0; o >>= 1) ss += __shfl_xor_sync(0xffffffffu, ss, o);
    float sc = 1.0f / fmaxf(sqrtf(ss), 1e-12f);
    a0 *= sc; a1 *= sc;
    a0 = a0 > 0.f ? a0 : 0.01f * a0;
    a1 = a1 > 0.f ? a1 : 0.01f * a1;
    *(float2*)&g_h[(size_t)gw * DIM + lane * 2] = make_float2(a0, a1);
}

// ------------------------- fp16 tensor-core dense GEMM ----------------------
// C[nrows,64] = act( A[nrows,K] @ W[K,64] (+bias) ) (+add)
// 128 threads = 4 warps, 64-row tile; warp computes 16x64 via m16n8k16 HMMA.
template<int K, int ACT, int HASB, int HASADD, int OUTHALF>
__global__ void __launch_bounds__(128)
k_mma(const float* __restrict__ Aext, int a_id,
      const float* __restrict__ W, const float* __restrict__ bias,
      int add_id,
      float* __restrict__ Cext, int c_id, int c_off,
      int nrows) {
    const float* A   = sel((float*)Aext, a_id);
    const float* add = HASADD ? sel(nullptr, add_id) : nullptr;
    float*       C   = OUTHALF ? nullptr : sel(Cext, c_id) + c_off;

    __shared__ __align__(16) __half As[64][K + 8];     // stride (K+8)*2 B ≡ 4 words mod 32
    __shared__ __align__(16) __half Wt[64][K + 8];     // W transposed: Wt[n][k]

    int row0 = blockIdx.x * 64;
    int t    = threadIdx.x;
    int lane = t & 31;
    int wrp  = t >> 5;          // 0..3 -> rows 16*wrp..+15
    int r    = lane >> 2;       // 0..7
    int qp   = lane & 3;        // 0..3

    // ---- stage A (fp32 -> fp16), zero-pad tail rows ----
    #pragma unroll
    for (int i = t; i < 64 * (K / 4); i += 128) {
        int row = i / (K / 4), c4 = i % (K / 4);
        float4 v = make_float4(0.f, 0.f, 0.f, 0.f);
        if (row0 + row < nrows)
            v = *(const float4*)&A[(size_t)(row0 + row) * K + c4 * 4];
        *(half2*)&As[row][c4 * 4]     = __floats2half2_rn(v.x, v.y);
        *(half2*)&As[row][c4 * 4 + 2] = __floats2half2_rn(v.z, v.w);
    }
    // ---- stage W transposed (fp32 -> fp16) ----
    #pragma unroll
    for (int i = t; i < K * 64; i += 128) {
        int k = i >> 6, n = i & 63;
        Wt[n][k] = __float2half_rn(W[i]);
    }
    __syncthreads();

    float acc[8][4];
    #pragma unroll
    for (int n = 0; n < 8; n++)
        #pragma unroll
        for (int j = 0; j < 4; j++) acc[n][j] = 0.f;

    #pragma unroll
    for (int kt = 0; kt < K / 16; kt++) {
        int kb = kt * 16 + qp * 2;
        uint32_t a0 = *(const uint32_t*)&As[wrp * 16 + r    ][kb    ];
        uint32_t a1 = *(const uint32_t*)&As[wrp * 16 + r + 8][kb    ];
        uint32_t a2 = *(const uint32_t*)&As[wrp * 16 + r    ][kb + 8];
        uint32_t a3 = *(const uint32_t*)&As[wrp * 16 + r + 8][kb + 8];
        #pragma unroll
        for (int n = 0; n < 8; n++) {
            uint32_t b0 = *(const uint32_t*)&Wt[n * 8 + r][kb    ];
            uint32_t b1 = *(const uint32_t*)&Wt[n * 8 + r][kb + 8];
            asm volatile(
                "mma.sync.aligned.m16n8k16.row.col.f32.f16.f16.f32 "
                "{%0,%1,%2,%3}, {%4,%5,%6,%7}, {%8,%9}, {%0,%1,%2,%3};"
                : "+f"(acc[n][0]), "+f"(acc[n][1]), "+f"(acc[n][2]), "+f"(acc[n][3])
                : "r"(a0), "r"(a1), "r"(a2), "r"(a3), "r"(b0), "r"(b1));
        }
    }

    // ---- epilogue ----
    int row_lo = row0 + wrp * 16 + r;
    int row_hi = row_lo + 8;
    #pragma unroll
    for (int n = 0; n < 8; n++) {
        int col = n * 8 + qp * 2;
        float2 bv = make_float2(0.f, 0.f);
        if (HASB) bv = *(const float2*)&bias[col];
        float2 lo = make_float2(acc[n][0] + bv.x, acc[n][1] + bv.y);
        float2 hi = make_float2(acc[n][2] + bv.x, acc[n][3] + bv.y);
        if (ACT) {
            lo.x = lo.x > 0.f ? lo.x : 0.01f * lo.x;
            lo.y = lo.y > 0.f ? lo.y : 0.01f * lo.y;
            hi.x = hi.x > 0.f ? hi.x : 0.01f * hi.x;
            hi.y = hi.y > 0.f ? hi.y : 0.01f * hi.y;
        }
        if (HASADD) {
            if (row_lo < nrows) {
                float2 a4 = *(const float2*)&add[(size_t)row_lo * DIM + col];
                lo.x += a4.x; lo.y += a4.y;
            }
            if (row_hi < nrows) {
                float2 a4 = *(const float2*)&add[(size_t)row_hi * DIM + col];
                hi.x += a4.x; hi.y += a4.y;
            }
        }
        if (OUTHALF) {
            if (row_lo < nrows)
                *(half2*)&g_xwh[(size_t)row_lo * DIM + col] = __floats2half2_rn(lo.x, lo.y);
            if (row_hi < nrows)
                *(half2*)&g_xwh[(size_t)row_hi * DIM + col] = __floats2half2_rn(hi.x, hi.y);
        } else {
            if (row_lo < nrows) *(float2*)&C[(size_t)row_lo * DIM + col] = lo;
            if (row_hi < nrows) *(float2*)&C[(size_t)row_hi * DIM + col] = hi;
        }
    }
}

// -------------------------------- launcher ----------------------------------
extern "C" void kernel_launch(void* const* d_in, const int* in_sizes, int n_in,
                              void* d_out, int out_size) {
    const float* features = (const float*)d_in[0];
    const float* pref     = (const float*)d_in[1];
    const int*   ei       = (const int*)d_in[2];      // int32 edge_index [2, E]
    const float* W[22];
    for (int i = 0; i < 22; i++) W[i] = (const float*)d_in[3 + i];
    int E = in_sizes[2] / 2;
    float* out = (float*)d_out;
    (void)n_in; (void)out_size;

    const int TB = 256;
    const int ID_X = 0, ID_H = 1, ID_XH = 2, EXT = -1;

    // ---- per-launch prep: degrees + dst-CSR ----
    k_zero  <<<cdiv(NN, TB), TB>>>(NN);
    k_count <<<cdiv(E,  TB), TB>>>(ei, E);
    k_dinv  <<<cdiv(NN, TB), TB>>>(NN);
    k_scan_a<<<NBLK, SCAN_B>>>();
    k_scan_b<<<1, 256>>>();
    k_scan_c<<<cdiv(NN, TB), TB>>>(E);
    k_fill  <<<cdiv(E,  TB), TB>>>(E);

    // ---- embedding: x = l2norm(concat(pref, features@mlp_w + mlp_b)) ----
    k_copy_pref<<<cdiv(NUSER * 16, TB), TB>>>((const float4*)pref, NUSER * 16);
    k_mma<DIMF, 0, 1, 0, 0><<<cdiv(NITEM, 64), 128>>>(features, EXT, W[0], W[1], -1,
                                                      nullptr, ID_X, NUSER * DIM, NITEM);
    k_norm<<<cdiv(NN * 32, TB), TB>>>(ID_X, ID_X, NN);

    auto conv = [&](const float* cw, const float* cb) {
        k_mma<DIM, 0, 0, 0, 1><<<cdiv(NN, 64), 128>>>(nullptr, ID_X, cw, nullptr, -1,
                                                      nullptr, -1, 0, NN);   // -> g_xwh
        k_gather<<<cdiv(NN * 32, TB), TB>>>(cb);
    };

    // layer 1
    conv(W[2], W[3]);
    k_mma<DIM, 1, 1, 0, 0><<<cdiv(NN, 64), 128>>>(nullptr, ID_H, W[4], W[5], -1,
                                                  nullptr, ID_X, 0, NN);
    // layer 2
    conv(W[6], W[7]);
    k_mma<DIM, 1, 1, 0, 0><<<cdiv(NN, 64), 128>>>(nullptr, ID_H, W[8], W[9], -1,
                                                  nullptr, ID_X, 0, NN);

    // mu head
    conv(W[10], W[11]);
    k_mma<DIM, 1, 1, 0, 0><<<cdiv(NN, 64), 128>>>(nullptr, ID_X, W[12], W[13], -1,
                                                  nullptr, ID_XH, 0, NN);
    k_mma<DIM, 0, 1, 1, 0><<<cdiv(NN, 64), 128>>>(nullptr, ID_H, W[14], W[15], ID_XH,
                                                  out, EXT, 0, NN);

    // logvar head
    conv(W[16], W[17]);
    k_mma<DIM, 1, 1, 0, 0><<<cdiv(NN, 64), 128>>>(nullptr, ID_X, W[18], W[19], -1,
                                                  nullptr, ID_XH, 0, NN);
    k_mma<DIM, 0, 1, 1, 0><<<cdiv(NN, 64), 128>>>(nullptr, ID_H, W[20], W[21], ID_XH,
                                                  out, EXT, NN * DIM, NN);
}